// round 11
// baseline (speedup 1.0000x reference)
#include <cuda_runtime.h>
#include <cuda_fp16.h>
#include <cstdint>

#define NN 100000
#define EMAX 3200000
#define HH 4
#define CC 8
#define HC 32
#define GG 512
#define FIN 128
#define NEG 0.2f

#define SB 1024
#define MB 98                        // mega grid: 98 blocks of 1024 (co-resident on 148 SMs)

// ---------------- scratch (static device globals; no allocation) ----------------
__device__ int      d_deg[NN];
__device__ int      d_rowoff[NN + 1];
__device__ int      d_cursor[NN];
__device__ int      d_csrsrc[EMAX];
__device__ int      d_bsum[MB];
__device__ __half   d_h16[NN * HC];      // fp16 transformed features, 64B rows
__device__ float    d_als[NN * HH];      // attention logits (src side), float4 rows
__device__ float    d_ald[NN * HH];      // attention logits (dst side), float4 rows
__device__ float    d_xbuf[NN * HC];     // layer activations (elu output), fp32
__device__ unsigned d_asmax[4 * HH];     // per-layer flipped-uint global max of al_s per head
__device__ float    d_gsum[GG * HC];
__device__ float    d_gcnt[GG];
__device__ int      d_is64_edge;
__device__ int      d_is64_batch;
__device__ volatile int d_bar1c;
__device__ volatile int d_bar2c;

// ---------------- helpers ----------------
__device__ __forceinline__ float lrelu(float x) { return fmaxf(x, NEG * x); }

__device__ __forceinline__ unsigned flipf(float f) {
    unsigned u = __float_as_uint(f);
    return (u & 0x80000000u) ? ~u : (u | 0x80000000u);
}
__device__ __forceinline__ float unflipf(unsigned u) {
    return (u & 0x80000000u) ? __uint_as_float(u ^ 0x80000000u) : __uint_as_float(~u);
}

// ---------------- launch 1: init (zero scratch, dtype detect, barrier counters) ----------------
__global__ void init_kernel(const unsigned* __restrict__ e, const unsigned* __restrict__ b) {
    int i = blockIdx.x * blockDim.x + threadIdx.x;
    if (i < NN) d_deg[i] = 0;
    if (i < GG * HC) d_gsum[i] = 0.f;
    if (i < GG) d_gcnt[i] = 0.f;
    if (i < 4 * HH) d_asmax[i] = 0u;
    if (i == 0) { d_bar1c = 0; d_bar2c = 0; }

    if (blockIdx.x == 0) {                     // 256 threads: dtype detection
        int t = threadIdx.x;
        int anyE = 0, anyB = 0;
        for (int k = t; k < 1024; k += 256) anyE |= (e[2 * k + 1] != 0u);
        for (int k = 2000 + t; k < 6000; k += 256) anyB |= (b[2 * k + 1] != 0u);
        __shared__ int sE, sB;
        if (t == 0) { sE = 0; sB = 0; }
        __syncthreads();
        if (anyE) atomicOr(&sE, 1);
        if (anyB) atomicOr(&sB, 1);
        __syncthreads();
        if (t == 0) { d_is64_edge = !sE; d_is64_batch = !sB; }
    }
}

// ---------------- launch 2: degree count ----------------
__global__ void count_kernel(const void* __restrict__ eidx, int E) {
    int e = blockIdx.x * blockDim.x + threadIdx.x;
    if (e >= E) return;
    int dst;
    if (d_is64_edge) dst = (int)((const long long*)eidx)[(size_t)E + e];
    else             dst = ((const int*)eidx)[(size_t)E + e];
    atomicAdd(&d_deg[dst], 1);
}

// ---------------- launch 3: mega = scan(1+2+3) + k1_first GEMM + scatter ----------------
// 98 blocks x 1024 threads, all co-resident (<=64 regs via launch_bounds, ~21KB smem)
// -> in-kernel grid barriers are deadlock-free.
__global__ void __launch_bounds__(1024, 1) mega_kernel(
        const void* __restrict__ eidx, int E,
        const float* __restrict__ x, const float* __restrict__ W,
        const float* __restrict__ as_, const float* __restrict__ ad_,
        unsigned* __restrict__ am) {
    __shared__ float sW[FIN * HC];             // 16KB
    __shared__ int sh[SB];                     // 4KB
    __shared__ int red[32];
    __shared__ unsigned smax[HH];
    int t = threadIdx.x, bid = blockIdx.x;
    int lane = t & 31, w = t >> 5;

    for (int i = t; i < FIN * HC; i += 1024) sW[i] = W[i];
    if (t < HH) smax[t] = 0u;

    // ---- P1: block sum of deg chunk ----
    int i0 = bid * SB + t;
    int v = (i0 < NN) ? d_deg[i0] : 0;
    {
        int s = v;
        s += __shfl_xor_sync(0xffffffffu, s, 1);
        s += __shfl_xor_sync(0xffffffffu, s, 2);
        s += __shfl_xor_sync(0xffffffffu, s, 4);
        s += __shfl_xor_sync(0xffffffffu, s, 8);
        s += __shfl_xor_sync(0xffffffffu, s, 16);
        if (lane == 0) red[w] = s;
        __syncthreads();
        if (t < 32) {
            int y = red[t];
            y += __shfl_xor_sync(0xffffffffu, y, 1);
            y += __shfl_xor_sync(0xffffffffu, y, 2);
            y += __shfl_xor_sync(0xffffffffu, y, 4);
            y += __shfl_xor_sync(0xffffffffu, y, 8);
            y += __shfl_xor_sync(0xffffffffu, y, 16);
            if (t == 0) d_bsum[bid] = y;
        }
    }
    // ---- grid barrier 1 ----
    __syncthreads();
    if (t == 0) {
        __threadfence();
        atomicAdd((int*)&d_bar1c, 1);
        while (d_bar1c < MB) { }
    }
    __syncthreads();

    // ---- P2: every block scans the 98 block sums locally (redundant, barrier-free) ----
    if (t < 128) sh[t] = (t < MB) ? d_bsum[t] : 0;
    __syncthreads();
    for (int off = 1; off < 128; off <<= 1) {
        int xv = (t >= off && t < 128) ? sh[t - off] : 0;
        __syncthreads();
        if (t < 128) sh[t] += xv;
        __syncthreads();
    }
    int base = (bid > 0) ? sh[bid - 1] : 0;
    if (bid == MB - 1 && t == 0) d_rowoff[NN] = sh[MB - 1];
    __syncthreads();

    // ---- P3: local exclusive scan of deg chunk + write rowoff/cursor ----
    sh[t] = v;
    __syncthreads();
    for (int off = 1; off < SB; off <<= 1) {
        int xv = (t >= off) ? sh[t - off] : 0;
        __syncthreads();
        sh[t] += xv;
        __syncthreads();
    }
    {
        int off = base + sh[t] - v;
        if (i0 < NN) { d_rowoff[i0] = off; d_cursor[i0] = off; }
    }

    // ---- k1_first GEMM: warp-per-node, strided over 3136 warps (no CSR dep) ----
    {
        float av_s = as_[lane], av_d = ad_[lane];
        unsigned rmax = 0u;
        int gw = bid * 32 + w;
        for (int n = gw; n < NN; n += MB * 32) {
            float4 xv = ((const float4*)(x + (size_t)n * FIN))[lane];
            float hc = 0.f;
#pragma unroll
            for (int k = 0; k < FIN; k++) {
                float comp = ((k & 3) == 0) ? xv.x : ((k & 3) == 1) ? xv.y : ((k & 3) == 2) ? xv.z : xv.w;
                float xk = __shfl_sync(0xffffffffu, comp, k >> 2);
                hc = fmaf(xk, sW[k * HC + lane], hc);
            }
            float ps = hc * av_s, pd = hc * av_d;
            ps += __shfl_xor_sync(0xffffffffu, ps, 1);
            ps += __shfl_xor_sync(0xffffffffu, ps, 2);
            ps += __shfl_xor_sync(0xffffffffu, ps, 4);
            pd += __shfl_xor_sync(0xffffffffu, pd, 1);
            pd += __shfl_xor_sync(0xffffffffu, pd, 2);
            pd += __shfl_xor_sync(0xffffffffu, pd, 4);
            d_h16[(size_t)n * HC + lane] = __float2half(hc);
            if ((lane & 7) == 0) {
                int head = lane >> 3;
                d_als[n * HH + head] = ps;
                d_ald[n * HH + head] = pd;
                unsigned f = flipf(ps);
                if (f > rmax) rmax = f;
            }
        }
        if ((lane & 7) == 0) atomicMax(&smax[lane >> 3], rmax);
    }

    // ---- grid barrier 2 (all cursors ready) ----
    __syncthreads();
    if (t == 0) {
        __threadfence();
        atomicAdd((int*)&d_bar2c, 1);
        while (d_bar2c < MB) { }
    }
    __syncthreads();

    // ---- P4: scatter edges (strided over 100352 threads) ----
    {
        int is64 = d_is64_edge;
        for (int e = bid * SB + t; e < E; e += MB * SB) {
            int s, dst;
            if (is64) {
                s   = (int)((const long long*)eidx)[e];
                dst = (int)((const long long*)eidx)[(size_t)E + e];
            } else {
                s   = ((const int*)eidx)[e];
                dst = ((const int*)eidx)[(size_t)E + e];
            }
            int pos = atomicAdd(&d_cursor[dst], 1);
            d_csrsrc[pos] = s;
        }
    }

    // ---- flush per-block asmax ----
    if (t < HH) atomicMax(&am[t], smax[t]);
}

// ---------------- per-layer node transform, layers 2-4 (unchanged from R10) ----------------
__global__ void k1_small_kernel(const float* __restrict__ W,
                                const float* __restrict__ as_, const float* __restrict__ ad_,
                                unsigned* __restrict__ am) {
    __shared__ float sW[HC * HC];
    __shared__ unsigned smax[HH];
    int t = threadIdx.x;                       // 256
    for (int i = t; i < HC * HC; i += 256) sW[i] = W[i];
    if (t < HH) smax[t] = 0u;
    __syncthreads();

    int lane = t & 31, w = t >> 5;
    int n = blockIdx.x * 8 + w;
    float av_s = as_[lane], av_d = ad_[lane];

    float xi = d_xbuf[(size_t)n * HC + lane];
    float hc = 0.f;
#pragma unroll
    for (int k = 0; k < HC; k++) {
        float xk = __shfl_sync(0xffffffffu, xi, k);
        hc = fmaf(xk, sW[k * HC + lane], hc);
    }

    float ps = hc * av_s, pd = hc * av_d;
    ps += __shfl_xor_sync(0xffffffffu, ps, 1);
    ps += __shfl_xor_sync(0xffffffffu, ps, 2);
    ps += __shfl_xor_sync(0xffffffffu, ps, 4);
    pd += __shfl_xor_sync(0xffffffffu, pd, 1);
    pd += __shfl_xor_sync(0xffffffffu, pd, 2);
    pd += __shfl_xor_sync(0xffffffffu, pd, 4);

    d_h16[(size_t)n * HC + lane] = __float2half(hc);
    int head = lane >> 3;
    if ((lane & 7) == 0) {
        d_als[n * HH + head] = ps;
        d_ald[n * HH + head] = pd;
        atomicMax(&smax[head], flipf(ps));
    }
    __syncthreads();
    if (t < HH) atomicMax(&am[t], smax[t]);
}

// ---------------- edge aggregation (unchanged from R10 best) ----------------
__global__ void edge_kernel(const float* __restrict__ bias, const unsigned* __restrict__ am) {
    __shared__ float4 sw[8][32];               // per-warp edge weights [j] = (w0..w3)
    int t = threadIdx.x, lane = t & 31, w = t >> 5;
    int d = blockIdx.x * 8 + w;                // grid 12500 exact
    int q = lane & 7, g = lane >> 3;
    int head = q >> 1;                         // head of this 4-channel group
    float4* swp = sw[w];
    const uint2* h2 = (const uint2*)d_h16;     // 8B = 4 fp16 channels
    const float4* als4 = (const float4*)d_als;

    float4 aldv = __ldg((const float4*)&d_ald[d * HH]);
    float m0 = lrelu(unflipf(am[0]) + aldv.x);
    float m1 = lrelu(unflipf(am[1]) + aldv.y);
    float m2 = lrelu(unflipf(am[2]) + aldv.z);
    float m3 = lrelu(unflipf(am[3]) + aldv.w);

    float4 alsd = __ldg(&als4[d]);
    float s0 = __expf(lrelu(alsd.x + aldv.x) - m0);
    float s1 = __expf(lrelu(alsd.y + aldv.y) - m1);
    float s2 = __expf(lrelu(alsd.z + aldv.z) - m2);
    float s3 = __expf(lrelu(alsd.w + aldv.w) - m3);
    float wselfq = (head == 0) ? s0 : (head == 1) ? s1 : (head == 2) ? s2 : s3;

    float4 acc = make_float4(0.f, 0.f, 0.f, 0.f);
    if (g == 0) {
        uint2 hv = __ldg(&h2[(size_t)d * 8 + q]);
        float2 f0 = __half22float2(*(const __half2*)&hv.x);
        float2 f1 = __half22float2(*(const __half2*)&hv.y);
        acc.x = wselfq * f0.x; acc.y = wselfq * f0.y;
        acc.z = wselfq * f1.x; acc.w = wselfq * f1.y;
    }
    float dn0 = 0.f, dn1 = 0.f, dn2 = 0.f, dn3 = 0.f;

    int beg = d_rowoff[d], end = d_rowoff[d + 1];
    for (int base = beg; base < end; base += 32) {
        int idx = base + lane;
        bool v = idx < end;
        int s = v ? __ldg(&d_csrsrc[idx]) : 0;
        float4 a = __ldg(&als4[s]);
        float w0 = __expf(lrelu(a.x + aldv.x) - m0);
        float w1 = __expf(lrelu(a.y + aldv.y) - m1);
        float w2 = __expf(lrelu(a.z + aldv.z) - m2);
        float w3 = __expf(lrelu(a.w + aldv.w) - m3);
        if (!v) { w0 = w1 = w2 = w3 = 0.f; }
        dn0 += w0; dn1 += w1; dn2 += w2; dn3 += w3;
        swp[lane] = make_float4(w0, w1, w2, w3);
        __syncwarp();

#pragma unroll
        for (int sub = 0; sub < 8; sub++) {
            int j = sub * 4 + g;
            int sj = __shfl_sync(0xffffffffu, s, j);
            uint2 hv = __ldg(&h2[(size_t)sj * 8 + q]);
            float wj = ((const float*)swp)[j * 4 + head];
            float2 f0 = __half22float2(*(const __half2*)&hv.x);
            float2 f1 = __half22float2(*(const __half2*)&hv.y);
            acc.x = fmaf(wj, f0.x, acc.x);
            acc.y = fmaf(wj, f0.y, acc.y);
            acc.z = fmaf(wj, f1.x, acc.z);
            acc.w = fmaf(wj, f1.y, acc.w);
        }
        __syncwarp();
    }

    acc.x += __shfl_xor_sync(0xffffffffu, acc.x, 8);
    acc.y += __shfl_xor_sync(0xffffffffu, acc.y, 8);
    acc.z += __shfl_xor_sync(0xffffffffu, acc.z, 8);
    acc.w += __shfl_xor_sync(0xffffffffu, acc.w, 8);
    acc.x += __shfl_xor_sync(0xffffffffu, acc.x, 16);
    acc.y += __shfl_xor_sync(0xffffffffu, acc.y, 16);
    acc.z += __shfl_xor_sync(0xffffffffu, acc.z, 16);
    acc.w += __shfl_xor_sync(0xffffffffu, acc.w, 16);

#pragma unroll
    for (int off = 1; off < 32; off <<= 1) {
        dn0 += __shfl_xor_sync(0xffffffffu, dn0, off);
        dn1 += __shfl_xor_sync(0xffffffffu, dn1, off);
        dn2 += __shfl_xor_sync(0xffffffffu, dn2, off);
        dn3 += __shfl_xor_sync(0xffffffffu, dn3, off);
    }

    if (lane < 8) {
        float dh = (head == 0) ? dn0 : (head == 1) ? dn1 : (head == 2) ? dn2 : dn3;
        float inv = 1.0f / (wselfq + dh);
        float4 bq = __ldg(&((const float4*)bias)[q]);
        float4 o;
        o.x = acc.x * inv + bq.x;
        o.y = acc.y * inv + bq.y;
        o.z = acc.z * inv + bq.z;
        o.w = acc.w * inv + bq.w;
        o.x = (o.x > 0.f) ? o.x : (__expf(o.x) - 1.f);
        o.y = (o.y > 0.f) ? o.y : (__expf(o.y) - 1.f);
        o.z = (o.z > 0.f) ? o.z : (__expf(o.z) - 1.f);
        o.w = (o.w > 0.f) ? o.w : (__expf(o.w) - 1.f);
        ((float4*)d_xbuf)[(size_t)d * 8 + q] = o;
    }
}

// ---------------- pooling (sorted batch: register-accumulate, flush on change) ----------------
__global__ void pool_kernel(const void* __restrict__ batch) {
    int t = threadIdx.x, lane = t & 31, w = t >> 5;
    int base = (blockIdx.x * 8 + w) * 32;
    if (base >= NN) return;
    int endn = base + 32; if (endn > NN) endn = NN;

    float acc = 0.f, cnt = 0.f;
    int gcur = -1;
    for (int n = base; n < endn; n++) {
        int g;
        if (d_is64_batch) g = (int)((const long long*)batch)[n];
        else              g = ((const int*)batch)[n];
        if (g != gcur) {
            if (gcur >= 0) {
                atomicAdd(&d_gsum[gcur * HC + lane], acc);
                if (lane == 0) atomicAdd(&d_gcnt[gcur], cnt);
            }
            gcur = g; acc = 0.f; cnt = 0.f;
        }
        acc += d_xbuf[(size_t)n * HC + lane];
        cnt += 1.f;
    }
    if (gcur >= 0) {
        atomicAdd(&d_gsum[gcur * HC + lane], acc);
        if (lane == 0) atomicAdd(&d_gcnt[gcur], cnt);
    }
}

__global__ void final_kernel(const float* __restrict__ fc_w, const float* __restrict__ fc_b,
                             float* __restrict__ out) {
    int g = blockIdx.x * blockDim.x + threadIdx.x;
    if (g >= GG) return;
    float inv = 1.0f / fmaxf(d_gcnt[g], 1.0f);
    float s = 0.f;
#pragma unroll
    for (int c = 0; c < HC; c++) s = fmaf(d_gsum[g * HC + c] * inv, fc_w[c], s);
    out[g] = s + fc_b[0];
}

// ---------------- launch ----------------
extern "C" void kernel_launch(void* const* d_in, const int* in_sizes, int n_in,
                              void* d_out, int out_size) {
    const float* x     = (const float*)d_in[0];
    const void*  eidx  = d_in[1];
    const void*  batch = d_in[2];
    const float* W1  = (const float*)d_in[3];
    const float* as1 = (const float*)d_in[4];
    const float* ad1 = (const float*)d_in[5];
    const float* b1  = (const float*)d_in[6];
    const float* fc_w = (const float*)d_in[19];
    const float* fc_b = (const float*)d_in[20];
    float* out = (float*)d_out;

    int E = in_sizes[1] / 2;
    if (E > EMAX) E = EMAX;
    if (E < 0) E = 0;

    const int NB = NN / 8;                 // 12500 blocks of 8 warps
    const int EB = (E + 255) / 256;

    unsigned* am_base = nullptr;
    cudaGetSymbolAddress((void**)&am_base, d_asmax);

    // 1: init (+detect)
    init_kernel<<<(NN + 255) / 256, 256>>>((const unsigned*)eidx, (const unsigned*)batch);
    // 2: degree count
    if (EB > 0) count_kernel<<<EB, 256>>>(eidx, E);
    // 3: mega = scans + k1_first + scatter
    mega_kernel<<<MB, SB>>>(eidx, E, x, W1, as1, ad1, am_base + 0 * HH);
    // 4: layer-1 edge (ncu capture slot)
    edge_kernel<<<NB, 256>>>(b1, am_base + 0 * HH);

    // layers 2-4
    for (int L = 1; L < 4; L++) {
        const float* W   = (const float*)d_in[3 + 4 * L];
        const float* as_ = (const float*)d_in[4 + 4 * L];
        const float* ad_ = (const float*)d_in[5 + 4 * L];
        const float* b_  = (const float*)d_in[6 + 4 * L];
        k1_small_kernel<<<NB, 256>>>(W, as_, ad_, am_base + L * HH);
        edge_kernel<<<NB, 256>>>(b_, am_base + L * HH);
    }

    // pool + fc
    pool_kernel<<<(NN + 255) / 256, 256>>>(batch);
    final_kernel<<<2, 256>>>(fc_w, fc_b, out);
}

// round 14
// speedup vs baseline: 1.0858x; 1.0858x over previous
#include <cuda_runtime.h>
#include <cuda_fp16.h>
#include <cstdint>

#define NN 100000
#define EMAX 3200000
#define HH 4
#define CC 8
#define HC 32
#define GG 512
#define FIN 128
#define NEG 0.2f

#define SB 1024
#define NBLK ((NN + SB - 1) / SB)   // 98

// ---------------- scratch (static device globals; no allocation) ----------------
__device__ int      d_deg[NN];
__device__ int      d_rowoff[NN + 1];
__device__ int      d_cursor[NN];
__device__ int      d_csrsrc[EMAX];
__device__ int      d_bsum[NBLK];
__device__ int      d_bbase[NBLK];
__device__ __half   d_h16[NN * HC];      // fp16 transformed features, 64B rows
__device__ float    d_als[NN * HH];      // attention logits (src side), float4 rows
__device__ float    d_ald[NN * HH];      // attention logits (dst side), float4 rows
__device__ float    d_xbuf[NN * HC];     // layer activations (elu output), fp32
__device__ unsigned d_asmax[4 * HH];     // per-layer flipped-uint global max of al_s per head
__device__ float    d_gsum[GG * HC];
__device__ float    d_gcnt[GG];
__device__ int      d_is64_edge;
__device__ int      d_is64_batch;

// ---------------- helpers ----------------
__device__ __forceinline__ float lrelu(float x) { return fmaxf(x, NEG * x); }

__device__ __forceinline__ unsigned flipf(float f) {
    unsigned u = __float_as_uint(f);
    return (u & 0x80000000u) ? ~u : (u | 0x80000000u);
}
__device__ __forceinline__ float unflipf(unsigned u) {
    return (u & 0x80000000u) ? __uint_as_float(u ^ 0x80000000u) : __uint_as_float(~u);
}

// ---------------- init: zero scratch + dtype detect ----------------
__global__ void init_kernel(const unsigned* __restrict__ e, const unsigned* __restrict__ b) {
    int i = blockIdx.x * blockDim.x + threadIdx.x;
    if (i < NN) d_deg[i] = 0;
    if (i < GG * HC) d_gsum[i] = 0.f;
    if (i < GG) d_gcnt[i] = 0.f;
    if (i < 4 * HH) d_asmax[i] = 0u;

    if (blockIdx.x == 0) {                     // 256 threads: dtype detection
        int t = threadIdx.x;
        int anyE = 0, anyB = 0;
        for (int k = t; k < 1024; k += 256) anyE |= (e[2 * k + 1] != 0u);
        for (int k = 2000 + t; k < 6000; k += 256) anyB |= (b[2 * k + 1] != 0u);
        __shared__ int sE, sB;
        if (t == 0) { sE = 0; sB = 0; }
        __syncthreads();
        if (anyE) atomicOr(&sE, 1);
        if (anyB) atomicOr(&sB, 1);
        __syncthreads();
        if (t == 0) { d_is64_edge = !sE; d_is64_batch = !sB; }
    }
}

// ---------------- CSR build ----------------
__global__ void count_kernel(const void* __restrict__ eidx, int E) {
    int e = blockIdx.x * blockDim.x + threadIdx.x;
    if (e >= E) return;
    int dst;
    if (d_is64_edge) dst = (int)((const long long*)eidx)[(size_t)E + e];
    else             dst = ((const int*)eidx)[(size_t)E + e];
    atomicAdd(&d_deg[dst], 1);
}

// phase 1: per-block sums of deg
__global__ void scan_part1() {
    __shared__ int red[32];
    int t = threadIdx.x;
    int i = blockIdx.x * SB + t;
    int v = (i < NN) ? d_deg[i] : 0;
    int s = v;
    s += __shfl_xor_sync(0xffffffffu, s, 1);
    s += __shfl_xor_sync(0xffffffffu, s, 2);
    s += __shfl_xor_sync(0xffffffffu, s, 4);
    s += __shfl_xor_sync(0xffffffffu, s, 8);
    s += __shfl_xor_sync(0xffffffffu, s, 16);
    if ((t & 31) == 0) red[t >> 5] = s;
    __syncthreads();
    if (t < 32) {
        int x = red[t];
        x += __shfl_xor_sync(0xffffffffu, x, 1);
        x += __shfl_xor_sync(0xffffffffu, x, 2);
        x += __shfl_xor_sync(0xffffffffu, x, 4);
        x += __shfl_xor_sync(0xffffffffu, x, 8);
        x += __shfl_xor_sync(0xffffffffu, x, 16);
        if (t == 0) d_bsum[blockIdx.x] = x;
    }
}

// phase 2: scan the 98 block sums
__global__ void scan_part2() {
    __shared__ int sh[128];
    int t = threadIdx.x;                       // 128
    int v = (t < NBLK) ? d_bsum[t] : 0;
    sh[t] = v;
    __syncthreads();
    for (int off = 1; off < 128; off <<= 1) {
        int x = (t >= off) ? sh[t - off] : 0;
        __syncthreads();
        sh[t] += x;
        __syncthreads();
    }
    if (t < NBLK) d_bbase[t] = sh[t] - v;      // exclusive base
    if (t == NBLK - 1) d_rowoff[NN] = sh[t];
}

// phase 3: local exclusive scan + base
__global__ void scan_part3() {
    __shared__ int sh[SB];
    int t = threadIdx.x;
    int i = blockIdx.x * SB + t;
    int v = (i < NN) ? d_deg[i] : 0;
    sh[t] = v;
    __syncthreads();
    for (int off = 1; off < SB; off <<= 1) {
        int x = (t >= off) ? sh[t - off] : 0;
        __syncthreads();
        sh[t] += x;
        __syncthreads();
    }
    int off = d_bbase[blockIdx.x] + sh[t] - v;
    if (i < NN) { d_rowoff[i] = off; d_cursor[i] = off; }
}

__global__ void scatter_kernel(const void* __restrict__ eidx, int E) {
    int e = blockIdx.x * blockDim.x + threadIdx.x;
    if (e >= E) return;
    int s, dst;
    if (d_is64_edge) {
        s   = (int)((const long long*)eidx)[e];
        dst = (int)((const long long*)eidx)[(size_t)E + e];
    } else {
        s   = ((const int*)eidx)[e];
        dst = ((const int*)eidx)[(size_t)E + e];
    }
    int pos = atomicAdd(&d_cursor[dst], 1);
    d_csrsrc[pos] = s;
}

// ---------------- per-layer node transform ----------------

// Layer 1: h = x @ W (128 -> 32), plus attention logits + global max(al_s)
__global__ void k1_first_kernel(const float* __restrict__ x, const float* __restrict__ W,
                                const float* __restrict__ as_, const float* __restrict__ ad_,
                                unsigned* __restrict__ am) {
    __shared__ float sW[FIN * HC];
    __shared__ unsigned smax[HH];
    int t = threadIdx.x;                       // 256
    for (int i = t; i < FIN * HC; i += 256) sW[i] = W[i];
    if (t < HH) smax[t] = 0u;
    __syncthreads();

    int lane = t & 31, w = t >> 5;
    int n = blockIdx.x * 8 + w;                // grid 12500 exact
    float av_s = as_[lane], av_d = ad_[lane];

    float4 xv = ((const float4*)(x + (size_t)n * FIN))[lane];
    float hc = 0.f;
#pragma unroll
    for (int k = 0; k < FIN; k++) {
        float comp = ((k & 3) == 0) ? xv.x : ((k & 3) == 1) ? xv.y : ((k & 3) == 2) ? xv.z : xv.w;
        float xk = __shfl_sync(0xffffffffu, comp, k >> 2);
        hc = fmaf(xk, sW[k * HC + lane], hc);
    }

    float ps = hc * av_s, pd = hc * av_d;
    ps += __shfl_xor_sync(0xffffffffu, ps, 1);
    ps += __shfl_xor_sync(0xffffffffu, ps, 2);
    ps += __shfl_xor_sync(0xffffffffu, ps, 4);
    pd += __shfl_xor_sync(0xffffffffu, pd, 1);
    pd += __shfl_xor_sync(0xffffffffu, pd, 2);
    pd += __shfl_xor_sync(0xffffffffu, pd, 4);

    d_h16[(size_t)n * HC + lane] = __float2half(hc);
    int head = lane >> 3;
    if ((lane & 7) == 0) {
        d_als[n * HH + head] = ps;
        d_ald[n * HH + head] = pd;
        atomicMax(&smax[head], flipf(ps));
    }
    __syncthreads();
    if (t < HH) atomicMax(&am[t], smax[t]);
}

// Layers 2-4: h = xbuf @ W (32 -> 32), same epilogue
__global__ void k1_small_kernel(const float* __restrict__ W,
                                const float* __restrict__ as_, const float* __restrict__ ad_,
                                unsigned* __restrict__ am) {
    __shared__ float sW[HC * HC];
    __shared__ unsigned smax[HH];
    int t = threadIdx.x;                       // 256
    for (int i = t; i < HC * HC; i += 256) sW[i] = W[i];
    if (t < HH) smax[t] = 0u;
    __syncthreads();

    int lane = t & 31, w = t >> 5;
    int n = blockIdx.x * 8 + w;
    float av_s = as_[lane], av_d = ad_[lane];

    float xi = d_xbuf[(size_t)n * HC + lane];
    float hc = 0.f;
#pragma unroll
    for (int k = 0; k < HC; k++) {
        float xk = __shfl_sync(0xffffffffu, xi, k);
        hc = fmaf(xk, sW[k * HC + lane], hc);
    }

    float ps = hc * av_s, pd = hc * av_d;
    ps += __shfl_xor_sync(0xffffffffu, ps, 1);
    ps += __shfl_xor_sync(0xffffffffu, ps, 2);
    ps += __shfl_xor_sync(0xffffffffu, ps, 4);
    pd += __shfl_xor_sync(0xffffffffu, pd, 1);
    pd += __shfl_xor_sync(0xffffffffu, pd, 2);
    pd += __shfl_xor_sync(0xffffffffu, pd, 4);

    d_h16[(size_t)n * HC + lane] = __float2half(hc);
    int head = lane >> 3;
    if ((lane & 7) == 0) {
        d_als[n * HH + head] = ps;
        d_ald[n * HH + head] = pd;
        atomicMax(&smax[head], flipf(ps));
    }
    __syncthreads();
    if (t < HH) atomicMax(&am[t], smax[t]);
}

// ---------------- edge aggregation: one warp per dst node (R10 structure, higher occ) ----------------
// ncu R11: L1=57%, issue=60%, occ=52% -> both ceilings latency-overlappable; push occupancy
// via __launch_bounds__(256, 6) (<=42 regs, 48 warps/SM) and trim live regs (single-exp self loop).
__global__ void __launch_bounds__(256, 6) edge_kernel(const float* __restrict__ bias,
                                                      const unsigned* __restrict__ am) {
    __shared__ float4 sw[8][32];               // per-warp edge weights [j] = (w0..w3)
    int t = threadIdx.x, lane = t & 31, w = t >> 5;
    int d = blockIdx.x * 8 + w;                // grid 12500 exact
    int q = lane & 7, g = lane >> 3;
    int head = q >> 1;                         // head of this 4-channel group
    float4* swp = sw[w];
    const uint2* h2 = (const uint2*)d_h16;     // 8B = 4 fp16 channels
    const float4* als4 = (const float4*)d_als;

    float4 aldv = __ldg((const float4*)&d_ald[d * HH]);
    float m0 = lrelu(unflipf(am[0]) + aldv.x);
    float m1 = lrelu(unflipf(am[1]) + aldv.y);
    float m2 = lrelu(unflipf(am[2]) + aldv.z);
    float m3 = lrelu(unflipf(am[3]) + aldv.w);

    // self-loop weight: single exp on this lane's own head
    float4 alsd = __ldg(&als4[d]);
    float alsh = (head == 0) ? alsd.x : (head == 1) ? alsd.y : (head == 2) ? alsd.z : alsd.w;
    float aldh = (head == 0) ? aldv.x : (head == 1) ? aldv.y : (head == 2) ? aldv.z : aldv.w;
    float mh   = (head == 0) ? m0 : (head == 1) ? m1 : (head == 2) ? m2 : m3;
    float wselfq = __expf(lrelu(alsh + aldh) - mh);

    float4 acc = make_float4(0.f, 0.f, 0.f, 0.f);
    if (g == 0) {
        uint2 hv = __ldg(&h2[(size_t)d * 8 + q]);
        float2 f0 = __half22float2(*(const __half2*)&hv.x);
        float2 f1 = __half22float2(*(const __half2*)&hv.y);
        acc.x = wselfq * f0.x; acc.y = wselfq * f0.y;
        acc.z = wselfq * f1.x; acc.w = wselfq * f1.y;
    }
    float dn0 = 0.f, dn1 = 0.f, dn2 = 0.f, dn3 = 0.f;

    int beg = d_rowoff[d], end = d_rowoff[d + 1];
    for (int base = beg; base < end; base += 32) {
        // phase A: lane j owns edge j — compute all 4 head weights
        int idx = base + lane;
        bool v = idx < end;
        int s = v ? __ldg(&d_csrsrc[idx]) : 0;
        float4 a = __ldg(&als4[s]);
        float w0 = __expf(lrelu(a.x + aldv.x) - m0);
        float w1 = __expf(lrelu(a.y + aldv.y) - m1);
        float w2 = __expf(lrelu(a.z + aldv.z) - m2);
        float w3 = __expf(lrelu(a.w + aldv.w) - m3);
        if (!v) { w0 = w1 = w2 = w3 = 0.f; }
        dn0 += w0; dn1 += w1; dn2 += w2; dn3 += w3;
        swp[lane] = make_float4(w0, w1, w2, w3);
        __syncwarp();

        // phase B: 4 edges per iteration; lane handles 4-channel group q of edge sub*4+g
#pragma unroll
        for (int sub = 0; sub < 8; sub++) {
            int j = sub * 4 + g;
            int sj = __shfl_sync(0xffffffffu, s, j);
            uint2 hv = __ldg(&h2[(size_t)sj * 8 + q]);
            float wj = ((const float*)swp)[j * 4 + head];
            float2 f0 = __half22float2(*(const __half2*)&hv.x);
            float2 f1 = __half22float2(*(const __half2*)&hv.y);
            acc.x = fmaf(wj, f0.x, acc.x);
            acc.y = fmaf(wj, f0.y, acc.y);
            acc.z = fmaf(wj, f1.x, acc.z);
            acc.w = fmaf(wj, f1.y, acc.w);
        }
        __syncwarp();
    }

    // reduce accumulators across the 4 edge-slot groups (same q)
    acc.x += __shfl_xor_sync(0xffffffffu, acc.x, 8);
    acc.y += __shfl_xor_sync(0xffffffffu, acc.y, 8);
    acc.z += __shfl_xor_sync(0xffffffffu, acc.z, 8);
    acc.w += __shfl_xor_sync(0xffffffffu, acc.w, 8);
    acc.x += __shfl_xor_sync(0xffffffffu, acc.x, 16);
    acc.y += __shfl_xor_sync(0xffffffffu, acc.y, 16);
    acc.z += __shfl_xor_sync(0xffffffffu, acc.z, 16);
    acc.w += __shfl_xor_sync(0xffffffffu, acc.w, 16);

    // reduce per-head denominators across all lanes
#pragma unroll
    for (int off = 1; off < 32; off <<= 1) {
        dn0 += __shfl_xor_sync(0xffffffffu, dn0, off);
        dn1 += __shfl_xor_sync(0xffffffffu, dn1, off);
        dn2 += __shfl_xor_sync(0xffffffffu, dn2, off);
        dn3 += __shfl_xor_sync(0xffffffffu, dn3, off);
    }

    if (lane < 8) {
        float dh = (head == 0) ? dn0 : (head == 1) ? dn1 : (head == 2) ? dn2 : dn3;
        float inv = 1.0f / (wselfq + dh);
        float4 bq = __ldg(&((const float4*)bias)[q]);
        float4 o;
        o.x = acc.x * inv + bq.x;
        o.y = acc.y * inv + bq.y;
        o.z = acc.z * inv + bq.z;
        o.w = acc.w * inv + bq.w;
        o.x = (o.x > 0.f) ? o.x : (__expf(o.x) - 1.f);
        o.y = (o.y > 0.f) ? o.y : (__expf(o.y) - 1.f);
        o.z = (o.z > 0.f) ? o.z : (__expf(o.z) - 1.f);
        o.w = (o.w > 0.f) ? o.w : (__expf(o.w) - 1.f);
        ((float4*)d_xbuf)[(size_t)d * 8 + q] = o;
    }
}

// ---------------- pooling (sorted batch: register-accumulate, flush on change) ----------------
__global__ void pool_kernel(const void* __restrict__ batch) {
    int t = threadIdx.x, lane = t & 31, w = t >> 5;
    int base = (blockIdx.x * 8 + w) * 32;
    if (base >= NN) return;
    int endn = base + 32; if (endn > NN) endn = NN;

    float acc = 0.f, cnt = 0.f;
    int gcur = -1;
    for (int n = base; n < endn; n++) {
        int g;
        if (d_is64_batch) g = (int)((const long long*)batch)[n];
        else              g = ((const int*)batch)[n];
        if (g != gcur) {
            if (gcur >= 0) {
                atomicAdd(&d_gsum[gcur * HC + lane], acc);
                if (lane == 0) atomicAdd(&d_gcnt[gcur], cnt);
            }
            gcur = g; acc = 0.f; cnt = 0.f;
        }
        acc += d_xbuf[(size_t)n * HC + lane];
        cnt += 1.f;
    }
    if (gcur >= 0) {
        atomicAdd(&d_gsum[gcur * HC + lane], acc);
        if (lane == 0) atomicAdd(&d_gcnt[gcur], cnt);
    }
}

__global__ void final_kernel(const float* __restrict__ fc_w, const float* __restrict__ fc_b,
                             float* __restrict__ out) {
    int g = blockIdx.x * blockDim.x + threadIdx.x;
    if (g >= GG) return;
    float inv = 1.0f / fmaxf(d_gcnt[g], 1.0f);
    float s = 0.f;
#pragma unroll
    for (int c = 0; c < HC; c++) s = fmaf(d_gsum[g * HC + c] * inv, fc_w[c], s);
    out[g] = s + fc_b[0];
}

// ---------------- launch ----------------
extern "C" void kernel_launch(void* const* d_in, const int* in_sizes, int n_in,
                              void* d_out, int out_size) {
    const float* x     = (const float*)d_in[0];
    const void*  eidx  = d_in[1];
    const void*  batch = d_in[2];
    const float* W1  = (const float*)d_in[3];
    const float* as1 = (const float*)d_in[4];
    const float* ad1 = (const float*)d_in[5];
    const float* b1  = (const float*)d_in[6];
    const float* fc_w = (const float*)d_in[19];
    const float* fc_b = (const float*)d_in[20];
    float* out = (float*)d_out;

    int E = in_sizes[1] / 2;
    if (E > EMAX) E = EMAX;
    if (E < 0) E = 0;

    const int NB = NN / 8;                 // 12500 blocks of 8 warps
    const int EB = (E + 255) / 256;

    unsigned* am_base = nullptr;
    cudaGetSymbolAddress((void**)&am_base, d_asmax);

    init_kernel<<<(NN + 255) / 256, 256>>>((const unsigned*)eidx, (const unsigned*)batch);

    // CSR build (parallel 3-phase scan)
    if (EB > 0) count_kernel<<<EB, 256>>>(eidx, E);
    scan_part1<<<NBLK, SB>>>();
    scan_part2<<<1, 128>>>();
    scan_part3<<<NBLK, SB>>>();
    if (EB > 0) scatter_kernel<<<EB, 256>>>(eidx, E);

    // Layer 1 (input dim 128)
    k1_first_kernel<<<NB, 256>>>(x, W1, as1, ad1, am_base + 0 * HH);
    edge_kernel<<<NB, 256>>>(b1, am_base + 0 * HH);

    // Layers 2-4 (input dim 32)
    for (int L = 1; L < 4; L++) {
        const float* W   = (const float*)d_in[3 + 4 * L];
        const float* as_ = (const float*)d_in[4 + 4 * L];
        const float* ad_ = (const float*)d_in[5 + 4 * L];
        const float* b_  = (const float*)d_in[6 + 4 * L];
        k1_small_kernel<<<NB, 256>>>(W, as_, ad_, am_base + L * HH);
        edge_kernel<<<NB, 256>>>(b_, am_base + L * HH);
    }

    // Global mean pool + FC
    pool_kernel<<<(NN + 255) / 256, 256>>>(batch);
    final_kernel<<<2, 256>>>(fc_w, fc_b, out);
}

// round 15
// speedup vs baseline: 1.1473x; 1.0567x over previous
#include <cuda_runtime.h>
#include <cuda_fp16.h>
#include <cstdint>

#define NN 100000
#define EMAX 3200000
#define HH 4
#define CC 8
#define HC 32
#define GG 512
#define FIN 128
#define NEG 0.2f

#define SB 1024
#define NBLK ((NN + SB - 1) / SB)   // 98

// ---------------- scratch (static device globals; no allocation) ----------------
__device__ int      d_deg[NN];
__device__ int      d_rowoff[NN + 1];
__device__ int      d_cursor[NN];
__device__ int      d_csrsrc[EMAX];
__device__ int      d_bsum[NBLK];
__device__ int      d_bbase[NBLK];
__device__ __half   d_h16[2][NN * HC];   // ping-pong fp16 features, 64B rows
__device__ float    d_als[2][NN * HH];   // ping-pong attention logits (src side)
__device__ float    d_ald[2][NN * HH];   // ping-pong attention logits (dst side)
__device__ float    d_xbuf[NN * HC];     // final-layer activations for pooling
__device__ unsigned d_asmax[4 * HH];     // per-layer flipped-uint global max of al_s per head
__device__ float    d_gsum[GG * HC];
__device__ float    d_gcnt[GG];
__device__ int      d_is64_edge;
__device__ int      d_is64_batch;

// ---------------- helpers ----------------
__device__ __forceinline__ float lrelu(float x) { return fmaxf(x, NEG * x); }

__device__ __forceinline__ unsigned flipf(float f) {
    unsigned u = __float_as_uint(f);
    return (u & 0x80000000u) ? ~u : (u | 0x80000000u);
}
__device__ __forceinline__ float unflipf(unsigned u) {
    return (u & 0x80000000u) ? __uint_as_float(u ^ 0x80000000u) : __uint_as_float(~u);
}

// ---------------- init: zero scratch + dtype detect ----------------
__global__ void init_kernel(const unsigned* __restrict__ e, const unsigned* __restrict__ b) {
    int i = blockIdx.x * blockDim.x + threadIdx.x;
    if (i < NN) d_deg[i] = 0;
    if (i < GG * HC) d_gsum[i] = 0.f;
    if (i < GG) d_gcnt[i] = 0.f;
    if (i < 4 * HH) d_asmax[i] = 0u;

    if (blockIdx.x == 0) {                     // 256 threads: dtype detection
        int t = threadIdx.x;
        int anyE = 0, anyB = 0;
        for (int k = t; k < 1024; k += 256) anyE |= (e[2 * k + 1] != 0u);
        for (int k = 2000 + t; k < 6000; k += 256) anyB |= (b[2 * k + 1] != 0u);
        __shared__ int sE, sB;
        if (t == 0) { sE = 0; sB = 0; }
        __syncthreads();
        if (anyE) atomicOr(&sE, 1);
        if (anyB) atomicOr(&sB, 1);
        __syncthreads();
        if (t == 0) { d_is64_edge = !sE; d_is64_batch = !sB; }
    }
}

// ---------------- CSR build ----------------
__global__ void count_kernel(const void* __restrict__ eidx, int E) {
    int e = blockIdx.x * blockDim.x + threadIdx.x;
    if (e >= E) return;
    int dst;
    if (d_is64_edge) dst = (int)((const long long*)eidx)[(size_t)E + e];
    else             dst = ((const int*)eidx)[(size_t)E + e];
    atomicAdd(&d_deg[dst], 1);
}

__global__ void scan_part1() {
    __shared__ int red[32];
    int t = threadIdx.x;
    int i = blockIdx.x * SB + t;
    int v = (i < NN) ? d_deg[i] : 0;
    int s = v;
    s += __shfl_xor_sync(0xffffffffu, s, 1);
    s += __shfl_xor_sync(0xffffffffu, s, 2);
    s += __shfl_xor_sync(0xffffffffu, s, 4);
    s += __shfl_xor_sync(0xffffffffu, s, 8);
    s += __shfl_xor_sync(0xffffffffu, s, 16);
    if ((t & 31) == 0) red[t >> 5] = s;
    __syncthreads();
    if (t < 32) {
        int x = red[t];
        x += __shfl_xor_sync(0xffffffffu, x, 1);
        x += __shfl_xor_sync(0xffffffffu, x, 2);
        x += __shfl_xor_sync(0xffffffffu, x, 4);
        x += __shfl_xor_sync(0xffffffffu, x, 8);
        x += __shfl_xor_sync(0xffffffffu, x, 16);
        if (t == 0) d_bsum[blockIdx.x] = x;
    }
}

__global__ void scan_part2() {
    __shared__ int sh[128];
    int t = threadIdx.x;                       // 128
    int v = (t < NBLK) ? d_bsum[t] : 0;
    sh[t] = v;
    __syncthreads();
    for (int off = 1; off < 128; off <<= 1) {
        int x = (t >= off) ? sh[t - off] : 0;
        __syncthreads();
        sh[t] += x;
        __syncthreads();
    }
    if (t < NBLK) d_bbase[t] = sh[t] - v;      // exclusive base
    if (t == NBLK - 1) d_rowoff[NN] = sh[t];
}

__global__ void scan_part3() {
    __shared__ int sh[SB];
    int t = threadIdx.x;
    int i = blockIdx.x * SB + t;
    int v = (i < NN) ? d_deg[i] : 0;
    sh[t] = v;
    __syncthreads();
    for (int off = 1; off < SB; off <<= 1) {
        int x = (t >= off) ? sh[t - off] : 0;
        __syncthreads();
        sh[t] += x;
        __syncthreads();
    }
    int off = d_bbase[blockIdx.x] + sh[t] - v;
    if (i < NN) { d_rowoff[i] = off; d_cursor[i] = off; }
}

__global__ void scatter_kernel(const void* __restrict__ eidx, int E) {
    int e = blockIdx.x * blockDim.x + threadIdx.x;
    if (e >= E) return;
    int s, dst;
    if (d_is64_edge) {
        s   = (int)((const long long*)eidx)[e];
        dst = (int)((const long long*)eidx)[(size_t)E + e];
    } else {
        s   = ((const int*)eidx)[e];
        dst = ((const int*)eidx)[(size_t)E + e];
    }
    int pos = atomicAdd(&d_cursor[dst], 1);
    d_csrsrc[pos] = s;
}

// ---------------- layer-1 node transform -> buffer 0 ----------------
__global__ void k1_first_kernel(const float* __restrict__ x, const float* __restrict__ W,
                                const float* __restrict__ as_, const float* __restrict__ ad_,
                                unsigned* __restrict__ am) {
    __shared__ float sW[FIN * HC];
    __shared__ unsigned smax[HH];
    int t = threadIdx.x;                       // 256
    for (int i = t; i < FIN * HC; i += 256) sW[i] = W[i];
    if (t < HH) smax[t] = 0u;
    __syncthreads();

    int lane = t & 31, w = t >> 5;
    int n = blockIdx.x * 8 + w;                // grid 12500 exact
    float av_s = as_[lane], av_d = ad_[lane];

    float4 xv = ((const float4*)(x + (size_t)n * FIN))[lane];
    float hc = 0.f;
#pragma unroll
    for (int k = 0; k < FIN; k++) {
        float comp = ((k & 3) == 0) ? xv.x : ((k & 3) == 1) ? xv.y : ((k & 3) == 2) ? xv.z : xv.w;
        float xk = __shfl_sync(0xffffffffu, comp, k >> 2);
        hc = fmaf(xk, sW[k * HC + lane], hc);
    }

    float ps = hc * av_s, pd = hc * av_d;
    ps += __shfl_xor_sync(0xffffffffu, ps, 1);
    ps += __shfl_xor_sync(0xffffffffu, ps, 2);
    ps += __shfl_xor_sync(0xffffffffu, ps, 4);
    pd += __shfl_xor_sync(0xffffffffu, pd, 1);
    pd += __shfl_xor_sync(0xffffffffu, pd, 2);
    pd += __shfl_xor_sync(0xffffffffu, pd, 4);

    d_h16[0][(size_t)n * HC + lane] = __float2half(hc);
    int head = lane >> 3;
    if ((lane & 7) == 0) {
        d_als[0][n * HH + head] = ps;
        d_ald[0][n * HH + head] = pd;
        atomicMax(&smax[head], flipf(ps));
    }
    __syncthreads();
    if (t < HH) atomicMax(&am[t], smax[t]);
}

// ---------------- edge aggregation + fused next-layer transform ----------------
// Reads buffer bin; when Wn != nullptr, computes the NEXT layer's h/als/ald into
// buffer bout inline (all lanes hold the full output after the xor reductions,
// so the 32x32 GEMM runs via shfl broadcast). Last layer (Wn==nullptr) writes xbuf.
__global__ void __launch_bounds__(256, 6) edge_kernel(
        const float* __restrict__ bias, const unsigned* __restrict__ am,
        int bin, int bout,
        const float* __restrict__ Wn, const float* __restrict__ asn,
        const float* __restrict__ adn, unsigned* __restrict__ amn) {
    __shared__ float4 sw[8][32];               // per-warp edge weights [j] = (w0..w3)
    __shared__ float sWn[HC * HC];
    __shared__ unsigned smax2[HH];
    int t = threadIdx.x, lane = t & 31, w = t >> 5;
    int d = blockIdx.x * 8 + w;                // grid 12500 exact
    int q = lane & 7, g = lane >> 3;
    int head = q >> 1;                         // head of this 4-channel group
    float4* swp = sw[w];
    const uint2* h2 = (const uint2*)d_h16[bin];
    const float4* als4 = (const float4*)d_als[bin];
    const float4* ald4 = (const float4*)d_ald[bin];

    bool fuse = (Wn != nullptr);
    if (fuse) for (int i = t; i < HC * HC; i += 256) sWn[i] = Wn[i];
    if (t < HH) smax2[t] = 0u;
    __syncthreads();

    float4 aldv = __ldg(&ald4[d]);
    float m0 = lrelu(unflipf(am[0]) + aldv.x);
    float m1 = lrelu(unflipf(am[1]) + aldv.y);
    float m2 = lrelu(unflipf(am[2]) + aldv.z);
    float m3 = lrelu(unflipf(am[3]) + aldv.w);

    // self-loop weight: single exp on this lane's own head
    float4 alsd = __ldg(&als4[d]);
    float alsh = (head == 0) ? alsd.x : (head == 1) ? alsd.y : (head == 2) ? alsd.z : alsd.w;
    float aldh = (head == 0) ? aldv.x : (head == 1) ? aldv.y : (head == 2) ? aldv.z : aldv.w;
    float mh   = (head == 0) ? m0 : (head == 1) ? m1 : (head == 2) ? m2 : m3;
    float wselfq = __expf(lrelu(alsh + aldh) - mh);

    float4 acc = make_float4(0.f, 0.f, 0.f, 0.f);
    if (g == 0) {
        uint2 hv = __ldg(&h2[(size_t)d * 8 + q]);
        float2 f0 = __half22float2(*(const __half2*)&hv.x);
        float2 f1 = __half22float2(*(const __half2*)&hv.y);
        acc.x = wselfq * f0.x; acc.y = wselfq * f0.y;
        acc.z = wselfq * f1.x; acc.w = wselfq * f1.y;
    }
    float dn0 = 0.f, dn1 = 0.f, dn2 = 0.f, dn3 = 0.f;

    int beg = d_rowoff[d], end = d_rowoff[d + 1];
    for (int base = beg; base < end; base += 32) {
        // phase A: lane j owns edge j — compute all 4 head weights
        int idx = base + lane;
        bool v = idx < end;
        int s = v ? __ldg(&d_csrsrc[idx]) : 0;
        float4 a = __ldg(&als4[s]);
        float w0 = __expf(lrelu(a.x + aldv.x) - m0);
        float w1 = __expf(lrelu(a.y + aldv.y) - m1);
        float w2 = __expf(lrelu(a.z + aldv.z) - m2);
        float w3 = __expf(lrelu(a.w + aldv.w) - m3);
        if (!v) { w0 = w1 = w2 = w3 = 0.f; }
        dn0 += w0; dn1 += w1; dn2 += w2; dn3 += w3;
        swp[lane] = make_float4(w0, w1, w2, w3);
        __syncwarp();

        // phase B: 4 edges per iteration; lane handles 4-channel group q of edge sub*4+g
#pragma unroll
        for (int sub = 0; sub < 8; sub++) {
            int j = sub * 4 + g;
            int sj = __shfl_sync(0xffffffffu, s, j);
            uint2 hv = __ldg(&h2[(size_t)sj * 8 + q]);
            float wj = ((const float*)swp)[j * 4 + head];
            float2 f0 = __half22float2(*(const __half2*)&hv.x);
            float2 f1 = __half22float2(*(const __half2*)&hv.y);
            acc.x = fmaf(wj, f0.x, acc.x);
            acc.y = fmaf(wj, f0.y, acc.y);
            acc.z = fmaf(wj, f1.x, acc.z);
            acc.w = fmaf(wj, f1.y, acc.w);
        }
        __syncwarp();
    }

    // reductions: butterflies leave the full sums in EVERY lane
    acc.x += __shfl_xor_sync(0xffffffffu, acc.x, 8);
    acc.y += __shfl_xor_sync(0xffffffffu, acc.y, 8);
    acc.z += __shfl_xor_sync(0xffffffffu, acc.z, 8);
    acc.w += __shfl_xor_sync(0xffffffffu, acc.w, 8);
    acc.x += __shfl_xor_sync(0xffffffffu, acc.x, 16);
    acc.y += __shfl_xor_sync(0xffffffffu, acc.y, 16);
    acc.z += __shfl_xor_sync(0xffffffffu, acc.z, 16);
    acc.w += __shfl_xor_sync(0xffffffffu, acc.w, 16);
#pragma unroll
    for (int off = 1; off < 32; off <<= 1) {
        dn0 += __shfl_xor_sync(0xffffffffu, dn0, off);
        dn1 += __shfl_xor_sync(0xffffffffu, dn1, off);
        dn2 += __shfl_xor_sync(0xffffffffu, dn2, off);
        dn3 += __shfl_xor_sync(0xffffffffu, dn3, off);
    }

    // output quad (valid in all lanes; lane L holds channels of q=L&7)
    float dh = (head == 0) ? dn0 : (head == 1) ? dn1 : (head == 2) ? dn2 : dn3;
    float inv = 1.0f / (wselfq + dh);
    float4 bq = __ldg(&((const float4*)bias)[q]);
    float4 o;
    o.x = acc.x * inv + bq.x;
    o.y = acc.y * inv + bq.y;
    o.z = acc.z * inv + bq.z;
    o.w = acc.w * inv + bq.w;
    o.x = (o.x > 0.f) ? o.x : (__expf(o.x) - 1.f);
    o.y = (o.y > 0.f) ? o.y : (__expf(o.y) - 1.f);
    o.z = (o.z > 0.f) ? o.z : (__expf(o.z) - 1.f);
    o.w = (o.w > 0.f) ? o.w : (__expf(o.w) - 1.f);

    if (!fuse) {
        if (lane < 8) ((float4*)d_xbuf)[(size_t)d * 8 + q] = o;
        return;                                // uniform across the grid
    }

    // ---- fused next-layer transform (== k1_small, input o via shfl broadcast) ----
    float av_s = asn[lane], av_d = adn[lane];
    float hc = 0.f;
#pragma unroll
    for (int k = 0; k < HC; k++) {
        float comp = ((k & 3) == 0) ? o.x : ((k & 3) == 1) ? o.y : ((k & 3) == 2) ? o.z : o.w;
        float xk = __shfl_sync(0xffffffffu, comp, k >> 2);
        hc = fmaf(xk, sWn[k * HC + lane], hc);
    }
    float ps = hc * av_s, pd = hc * av_d;
    ps += __shfl_xor_sync(0xffffffffu, ps, 1);
    ps += __shfl_xor_sync(0xffffffffu, ps, 2);
    ps += __shfl_xor_sync(0xffffffffu, ps, 4);
    pd += __shfl_xor_sync(0xffffffffu, pd, 1);
    pd += __shfl_xor_sync(0xffffffffu, pd, 2);
    pd += __shfl_xor_sync(0xffffffffu, pd, 4);

    d_h16[bout][(size_t)d * HC + lane] = __float2half(hc);
    int headc = lane >> 3;                     // channel-layout head
    if ((lane & 7) == 0) {
        d_als[bout][d * HH + headc] = ps;
        d_ald[bout][d * HH + headc] = pd;
        atomicMax(&smax2[headc], flipf(ps));
    }
    __syncthreads();
    if (t < HH) atomicMax(&amn[t], smax2[t]);
}

// ---------------- pooling (sorted batch: register-accumulate, flush on change) ----------------
__global__ void pool_kernel(const void* __restrict__ batch) {
    int t = threadIdx.x, lane = t & 31, w = t >> 5;
    int base = (blockIdx.x * 8 + w) * 32;
    if (base >= NN) return;
    int endn = base + 32; if (endn > NN) endn = NN;

    float acc = 0.f, cnt = 0.f;
    int gcur = -1;
    for (int n = base; n < endn; n++) {
        int g;
        if (d_is64_batch) g = (int)((const long long*)batch)[n];
        else              g = ((const int*)batch)[n];
        if (g != gcur) {
            if (gcur >= 0) {
                atomicAdd(&d_gsum[gcur * HC + lane], acc);
                if (lane == 0) atomicAdd(&d_gcnt[gcur], cnt);
            }
            gcur = g; acc = 0.f; cnt = 0.f;
        }
        acc += d_xbuf[(size_t)n * HC + lane];
        cnt += 1.f;
    }
    if (gcur >= 0) {
        atomicAdd(&d_gsum[gcur * HC + lane], acc);
        if (lane == 0) atomicAdd(&d_gcnt[gcur], cnt);
    }
}

__global__ void final_kernel(const float* __restrict__ fc_w, const float* __restrict__ fc_b,
                             float* __restrict__ out) {
    int g = blockIdx.x * blockDim.x + threadIdx.x;
    if (g >= GG) return;
    float inv = 1.0f / fmaxf(d_gcnt[g], 1.0f);
    float s = 0.f;
#pragma unroll
    for (int c = 0; c < HC; c++) s = fmaf(d_gsum[g * HC + c] * inv, fc_w[c], s);
    out[g] = s + fc_b[0];
}

// ---------------- launch ----------------
extern "C" void kernel_launch(void* const* d_in, const int* in_sizes, int n_in,
                              void* d_out, int out_size) {
    const float* x     = (const float*)d_in[0];
    const void*  eidx  = d_in[1];
    const void*  batch = d_in[2];
    const float* W1  = (const float*)d_in[3];
    const float* as1 = (const float*)d_in[4];
    const float* ad1 = (const float*)d_in[5];
    const float* fc_w = (const float*)d_in[19];
    const float* fc_b = (const float*)d_in[20];
    float* out = (float*)d_out;

    int E = in_sizes[1] / 2;
    if (E > EMAX) E = EMAX;
    if (E < 0) E = 0;

    const int NB = NN / 8;                 // 12500 blocks of 8 warps
    const int EB = (E + 255) / 256;

    unsigned* am_base = nullptr;
    cudaGetSymbolAddress((void**)&am_base, d_asmax);

    init_kernel<<<(NN + 255) / 256, 256>>>((const unsigned*)eidx, (const unsigned*)batch);

    // CSR build (parallel 3-phase scan)
    if (EB > 0) count_kernel<<<EB, 256>>>(eidx, E);
    scan_part1<<<NBLK, SB>>>();
    scan_part2<<<1, 128>>>();
    scan_part3<<<NBLK, SB>>>();
    if (EB > 0) scatter_kernel<<<EB, 256>>>(eidx, E);

    // Layer 1 node transform -> buffer 0
    k1_first_kernel<<<NB, 256>>>(x, W1, as1, ad1, am_base + 0 * HH);

    // Edge layers: L=0..2 fuse the next layer's transform (ping-pong buffers);
    // L=3 writes xbuf for pooling.
    int bin = 0;
    for (int L = 0; L < 4; L++) {
        const float* b_ = (const float*)d_in[6 + 4 * L];
        int bout = bin ^ 1;
        if (L < 3) {
            const float* Wn  = (const float*)d_in[3 + 4 * (L + 1)];
            const float* asn = (const float*)d_in[4 + 4 * (L + 1)];
            const float* adn = (const float*)d_in[5 + 4 * (L + 1)];
            edge_kernel<<<NB, 256>>>(b_, am_base + L * HH, bin, bout,
                                     Wn, asn, adn, am_base + (L + 1) * HH);
        } else {
            edge_kernel<<<NB, 256>>>(b_, am_base + L * HH, bin, bout,
                                     nullptr, nullptr, nullptr, nullptr);
        }
        bin = bout;
    }

    // Global mean pool + FC
    pool_kernel<<<(NN + 255) / 256, 256>>>(batch);
    final_kernel<<<2, 256>>>(fc_w, fc_b, out);
}